// round 2
// baseline (speedup 1.0000x reference)
#include <cuda_runtime.h>
#include <cstdint>
#include <math.h>

// Problem constants (fixed shapes for this problem instance)
#define BS 16
#define MG 32          // number of GT boxes per image
#define AN 8400        // anchors
#define NC 80          // classes
#define TK 10          // top-k
#define EPS_T 1e-9f    // EPS
#define CEPS  1e-7f    // CIOU_EPS

// Scratch (device globals — no allocation allowed)
__device__ float    g_overlaps[BS * MG * AN];   // 17.2 MB
__device__ float    g_align   [BS * MG * AN];   // 17.2 MB
__device__ unsigned g_posbits [BS * AN];        // bit m set -> gt m assigned
__device__ float    g_gmm     [BS * MG];
__device__ float    g_gmo     [BS * MG];

// ---------------------------------------------------------------------------
// K0: zero the per-call scratch
// ---------------------------------------------------------------------------
__global__ void kZero() {
    int i = blockIdx.x * blockDim.x + threadIdx.x;
    if (i < BS * AN) g_posbits[i] = 0u;
    if (i < BS * MG) { g_gmm[i] = 0.0f; g_gmo[i] = 0.0f; }
}

// ---------------------------------------------------------------------------
// K1: per (b, m): compute overlaps (CIoU) and align metric over all anchors,
//     per-row top-k (exact jax.lax.top_k tie-break: value desc, index asc),
//     set pos bits = topk & in_gts & gt_mask.
// ---------------------------------------------------------------------------
__device__ __forceinline__ bool pair_better(float v1, int i1, float v2, int i2) {
    return (v1 > v2) || (v1 == v2 && i1 < i2);
}

__global__ __launch_bounds__(256) void kAlign(
    const float* __restrict__ scores,   // (BS, AN, NC)
    const float* __restrict__ pdb,      // (BS, AN, 4)
    const float* __restrict__ anc,      // (AN, 2)
    const int*   __restrict__ glab,     // (BS, MG)
    const float* __restrict__ gbox,     // (BS, MG, 4)
    const float* __restrict__ gmask)    // (BS, MG)
{
    const int m = blockIdx.x;
    const int b = blockIdx.y;
    const int t = threadIdx.x;

    const float4 gb = ((const float4*)gbox)[b * MG + m];
    const float  gm = gmask[b * MG + m];
    const int    lab = glab[b * MG + m];

    const float w1 = gb.z - gb.x;
    const float h1 = gb.w - gb.y + CEPS;
    const float at1 = atanf(w1 / h1);
    const float area1 = w1 * h1;
    const float c_4pi2 = (float)(4.0 / (M_PI * M_PI));

    const float*  sc_b = scores + (size_t)b * AN * NC;
    const float4* pb_b = (const float4*)(pdb + (size_t)b * AN * 4);
    float* ov_row = g_overlaps + ((size_t)b * MG + m) * AN;
    float* al_row = g_align    + ((size_t)b * MG + m) * AN;

    // per-thread top-k (sorted descending under (value desc, index asc))
    float tv[TK]; int ti[TK];
#pragma unroll
    for (int i = 0; i < TK; i++) { tv[i] = -1.0f; ti[i] = 0x7fffffff; }

    for (int a = t; a < AN; a += blockDim.x) {
        const float2 ap = ((const float2*)anc)[a];
        const float4 pb = pb_b[a];

        // in_gts: min delta > EPS
        const float dmin = fminf(fminf(ap.x - gb.x, ap.y - gb.y),
                                 fminf(gb.z - ap.x, gb.w - ap.y));
        const float ing   = (dmin > EPS_T) ? 1.0f : 0.0f;
        const float valid = ing * gm;

        // CIoU(gt=box1, pd=box2)
        const float w2 = pb.z - pb.x;
        const float h2 = pb.w - pb.y + CEPS;
        const float iw = fminf(gb.z, pb.z) - fmaxf(gb.x, pb.x);
        const float ih = fminf(gb.w, pb.w) - fmaxf(gb.y, pb.y);
        const float inter = fmaxf(iw, 0.0f) * fmaxf(ih, 0.0f);
        const float uni   = area1 + w2 * h2 - inter + CEPS;
        const float iou   = inter / uni;
        const float cw = fmaxf(gb.z, pb.z) - fminf(gb.x, pb.x);
        const float ch = fmaxf(gb.w, pb.w) - fminf(gb.y, pb.y);
        const float c2 = cw * cw + ch * ch + CEPS;
        const float dx = pb.x + pb.z - gb.x - gb.z;
        const float dy = pb.y + pb.w - gb.y - gb.w;
        const float rho2 = (dx * dx + dy * dy) * 0.25f;
        const float dat = atanf(w2 / h2) - at1;
        const float v   = c_4pi2 * dat * dat;
        const float aa  = v / (v - iou + (1.0f + CEPS));
        const float ciou = iou - (rho2 / c2 + v * aa);

        const float ov = fmaxf(ciou, 0.0f) * valid;
        const float sc = sc_b[(size_t)a * NC + lab];
        const float o2 = ov * ov;
        const float al = sc * (o2 * o2 * o2) * valid;

        ov_row[a] = ov;
        al_row[a] = al;

        // top-k insertion
        if (pair_better(al, a, tv[TK - 1], ti[TK - 1])) {
            int j = TK - 1;
            while (j > 0 && pair_better(al, a, tv[j - 1], ti[j - 1])) {
                tv[j] = tv[j - 1]; ti[j] = ti[j - 1]; j--;
            }
            tv[j] = al; ti[j] = a;
        }
    }

    // block tree-merge of sorted top-k lists
    __shared__ float sv[256 * TK];
    __shared__ int   si[256 * TK];
#pragma unroll
    for (int i = 0; i < TK; i++) { sv[t * TK + i] = tv[i]; si[t * TK + i] = ti[i]; }
    __syncthreads();

    for (int s = 128; s >= 1; s >>= 1) {
        if (t < s) {
            float av[TK], bv[TK], rv[TK];
            int   ai[TK], bi[TK], ri[TK];
#pragma unroll
            for (int i = 0; i < TK; i++) {
                av[i] = sv[t * TK + i];       ai[i] = si[t * TK + i];
                bv[i] = sv[(t + s) * TK + i]; bi[i] = si[(t + s) * TK + i];
            }
            int ia = 0, ib = 0;
#pragma unroll
            for (int k = 0; k < TK; k++) {
                const bool takeA = pair_better(av[ia], ai[ia], bv[ib], bi[ib]);
                if (takeA) { rv[k] = av[ia]; ri[k] = ai[ia]; ia++; }
                else       { rv[k] = bv[ib]; ri[k] = bi[ib]; ib++; }
            }
#pragma unroll
            for (int i = 0; i < TK; i++) { sv[t * TK + i] = rv[i]; si[t * TK + i] = ri[i]; }
        }
        __syncthreads();
    }

    // threads 0..TK-1 set pos bits (topk_mask * in_gts * gt_mask)
    if (t < TK && gm != 0.0f) {
        const int a = si[t];
        const float2 ap = ((const float2*)anc)[a];
        const float dmin = fminf(fminf(ap.x - gb.x, ap.y - gb.y),
                                 fminf(gb.z - ap.x, gb.w - ap.y));
        if (dmin > EPS_T) {
            atomicOr(&g_posbits[b * AN + a], 1u << m);
        }
    }
}

// ---------------------------------------------------------------------------
// K2: per (b, a): resolve multi-assignment via overlaps argmax (first-max),
//     compute fg, tgt, write t_bboxes + fg, accumulate gmm/gmo row maxima.
// ---------------------------------------------------------------------------
__global__ __launch_bounds__(256) void kResolve(
    const float* __restrict__ gbox,     // (BS, MG, 4)
    float* __restrict__ out)            // packed output
{
    const int idx = blockIdx.x * blockDim.x + threadIdx.x;
    if (idx >= BS * AN) return;
    const int b = idx / AN;
    const int a = idx - b * AN;

    unsigned bits = g_posbits[idx];
    const int fg0 = __popc(bits);
    if (fg0 > 1) {
        // jnp.argmax over m: first occurrence of maximum (strict > scan)
        const float* ov = g_overlaps + (size_t)b * MG * AN + a;
        float best = ov[0];
        int bm = 0;
#pragma unroll 4
        for (int m = 1; m < MG; m++) {
            const float o = ov[(size_t)m * AN];
            if (o > best) { best = o; bm = m; }
        }
        bits = 1u << bm;
    }
    const int fg  = bits ? 1 : 0;
    const int tgt = bits ? (__ffs(bits) - 1) : 0;

    // t_bboxes (written for ALL anchors, even fg=0 -> gt_bboxes[0])
    float4* out_tb = (float4*)out;
    out_tb[idx] = ((const float4*)gbox)[b * MG + tgt];

    // fg (float 0/1), located after tb and tl blocks
    float* out_fg = out + (size_t)BS * AN * (4 + NC);
    out_fg[idx] = (float)fg;

    g_posbits[idx] = bits;

    if (bits) {
        const size_t off = ((size_t)b * MG + tgt) * AN + a;
        const float al = g_align[off];
        const float ov = g_overlaps[off];
        atomicMax((int*)&g_gmm[b * MG + tgt], __float_as_int(al));  // nonneg floats
        atomicMax((int*)&g_gmo[b * MG + tgt], __float_as_int(ov));
    }
}

// ---------------------------------------------------------------------------
// K3: per (b, a): t_labels scatter (tl region pre-zeroed by memset)
// ---------------------------------------------------------------------------
__global__ __launch_bounds__(256) void kLabels(
    const int* __restrict__ glab,       // (BS, MG)
    float* __restrict__ out)
{
    const int idx = blockIdx.x * blockDim.x + threadIdx.x;
    if (idx >= BS * AN) return;
    const unsigned bits = g_posbits[idx];
    if (!bits) return;
    const int b = idx / AN;
    const int a = idx - b * AN;
    const int m = __ffs(bits) - 1;

    const size_t off = ((size_t)b * MG + m) * AN + a;
    const float al = g_align[off];
    const float norm = al * g_gmo[b * MG + m] / (g_gmm[b * MG + m] + EPS_T);
    const int cls = glab[b * MG + m];

    float* out_tl = out + (size_t)BS * AN * 4;
    out_tl[(size_t)idx * NC + cls] = norm;
}

// ---------------------------------------------------------------------------
extern "C" void kernel_launch(void* const* d_in, const int* in_sizes, int n_in,
                              void* d_out, int out_size)
{
    const float* scores = (const float*)d_in[0];   // (16, 8400, 80)
    const float* pdb    = (const float*)d_in[1];   // (16, 8400, 4)
    const float* anc    = (const float*)d_in[2];   // (8400, 2)
    const int*   glab   = (const int*)  d_in[3];   // (16, 32, 1)
    const float* gbox   = (const float*)d_in[4];   // (16, 32, 4)
    const float* gmask  = (const float*)d_in[5];   // (16, 32, 1)
    float* out = (float*)d_out;

    // zero the whole output (t_labels is mostly zeros; fg mostly 0)
    cudaMemsetAsync(d_out, 0, (size_t)out_size * sizeof(float), 0);
    kZero<<<(BS * AN + 255) / 256, 256>>>();

    dim3 gA(MG, BS);
    kAlign<<<gA, 256>>>(scores, pdb, anc, glab, gbox, gmask);

    const int nBA = (BS * AN + 255) / 256;
    kResolve<<<nBA, 256>>>(gbox, out);
    kLabels<<<nBA, 256>>>(glab, out);
}